// round 4
// baseline (speedup 1.0000x reference)
#include <cuda_runtime.h>
#include <math.h>

#define BATCH 8192
#define NC    2048
#define NF    512

// Scratch (no allocations allowed in kernel_launch)
__device__ float g_xsq[BATCH];   // ||x_m||^2
__device__ float g_csq[NC];      // ||c_n||^2
__device__ float g_inv2s[NC];    // 1 / (2 * sigma_n^2)

// One warp per row: sum of squares of NF floats.
__global__ void row_norms_kernel(const float* __restrict__ X,
                                 float* __restrict__ out, int rows) {
    int warps_per_blk = blockDim.x >> 5;
    int row  = blockIdx.x * warps_per_blk + (threadIdx.x >> 5);
    int lane = threadIdx.x & 31;
    if (row >= rows) return;
    const float4* p = reinterpret_cast<const float4*>(X + (size_t)row * NF);
    float s = 0.f;
    #pragma unroll 4
    for (int i = lane; i < NF / 4; i += 32) {
        float4 v = p[i];
        s += v.x * v.x + v.y * v.y + v.z * v.z + v.w * v.w;
    }
    #pragma unroll
    for (int o = 16; o; o >>= 1) s += __shfl_xor_sync(0xffffffffu, s, o);
    if (lane == 0) out[row] = s;
}

__global__ void sigma_kernel(const float* __restrict__ sig,
                             float* __restrict__ out, int n) {
    int i = blockIdx.x * blockDim.x + threadIdx.x;
    if (i < n) {
        float s = sig[i];
        out[i] = 1.0f / (2.0f * s * s);
    }
}

// Register-tiled SGEMM (C = A * B^T), RBF epilogue fused.
// BM=BN=128, BK=16, 256 threads, 8x8 per-thread microtile.
__global__ __launch_bounds__(256, 2)
void rbf_gemm_kernel(const float* __restrict__ A,   // [BATCH, NF]
                     const float* __restrict__ B,   // [NC, NF]
                     const float* __restrict__ xsq,
                     const float* __restrict__ csq,
                     const float* __restrict__ inv2s,
                     float* __restrict__ C)         // [BATCH, NC]
{
    constexpr int BM = 128, BN = 128, BK = 16;
    // Pad so row stride (132 floats = 528B) stays 16B-aligned and spreads banks.
    __shared__ float As[BK][BM + 4];
    __shared__ float Bs[BK][BN + 4];

    const int bx = blockIdx.x;          // N tile
    const int by = blockIdx.y;          // M tile
    const int tid = threadIdx.x;
    const int tx = tid & 15;            // n-direction (0..15)
    const int ty = tid >> 4;            // m-direction (0..15)

    const float* Ab = A + (size_t)by * BM * NF;
    const float* Bb = B + (size_t)bx * BN * NF;

    float acc[8][8];
    #pragma unroll
    for (int m = 0; m < 8; m++)
        #pragma unroll
        for (int n = 0; n < 8; n++) acc[m][n] = 0.f;

    for (int k0 = 0; k0 < NF; k0 += BK) {
        // Each thread loads 2 float4 from A and 2 from B (tile = 512 float4 each).
        #pragma unroll
        for (int i = 0; i < 2; i++) {
            int idx = tid * 2 + i;           // 0..511
            int row = idx >> 2;              // 0..127
            int c4  = idx & 3;               // which float4 within the 16-wide row
            float4 va = *reinterpret_cast<const float4*>(Ab + (size_t)row * NF + k0 + c4 * 4);
            As[c4 * 4 + 0][row] = va.x;
            As[c4 * 4 + 1][row] = va.y;
            As[c4 * 4 + 2][row] = va.z;
            As[c4 * 4 + 3][row] = va.w;
            float4 vb = *reinterpret_cast<const float4*>(Bb + (size_t)row * NF + k0 + c4 * 4);
            Bs[c4 * 4 + 0][row] = vb.x;
            Bs[c4 * 4 + 1][row] = vb.y;
            Bs[c4 * 4 + 2][row] = vb.z;
            Bs[c4 * 4 + 3][row] = vb.w;
        }
        __syncthreads();

        #pragma unroll
        for (int k = 0; k < BK; k++) {
            float ra[8], rb[8];
            #pragma unroll
            for (int m = 0; m < 8; m++) ra[m] = As[k][ty * 8 + m];
            #pragma unroll
            for (int n = 0; n < 8; n++) rb[n] = Bs[k][tx * 8 + n];
            #pragma unroll
            for (int m = 0; m < 8; m++)
                #pragma unroll
                for (int n = 0; n < 8; n++)
                    acc[m][n] = fmaf(ra[m], rb[n], acc[m][n]);
        }
        __syncthreads();
    }

    // Fused RBF epilogue.
    const int m0 = by * BM + ty * 8;
    const int n0 = bx * BN + tx * 8;
    float cn[8], is[8];
    #pragma unroll
    for (int n = 0; n < 8; n++) { cn[n] = csq[n0 + n]; is[n] = inv2s[n0 + n]; }

    #pragma unroll
    for (int m = 0; m < 8; m++) {
        float xm = xsq[m0 + m];
        float res[8];
        #pragma unroll
        for (int n = 0; n < 8; n++) {
            float d = fmaf(-2.0f, acc[m][n], xm + cn[n]);
            d = fmaxf(d, 0.0f);
            res[n] = expf(-d * is[n]);
        }
        float* crow = C + (size_t)(m0 + m) * NC + n0;
        *reinterpret_cast<float4*>(crow + 0) = make_float4(res[0], res[1], res[2], res[3]);
        *reinterpret_cast<float4*>(crow + 4) = make_float4(res[4], res[5], res[6], res[7]);
    }
}

extern "C" void kernel_launch(void* const* d_in, const int* in_sizes, int n_in,
                              void* d_out, int out_size) {
    const float* inputs  = (const float*)d_in[0];   // [8192, 512]
    const float* centers = (const float*)d_in[1];   // [2048, 512]
    const float* sigmas  = (const float*)d_in[2];   // [2048]
    float* out = (float*)d_out;                     // [8192, 2048]

    float *xsq, *csq, *inv2s;
    cudaGetSymbolAddress((void**)&xsq,   g_xsq);
    cudaGetSymbolAddress((void**)&csq,   g_csq);
    cudaGetSymbolAddress((void**)&inv2s, g_inv2s);

    // Norms: one warp per row, 8 warps per block.
    row_norms_kernel<<<BATCH / 8, 256>>>(inputs, xsq, BATCH);
    row_norms_kernel<<<NC / 8, 256>>>(centers, csq, NC);
    sigma_kernel<<<NC / 256, 256>>>(sigmas, inv2s, NC);

    dim3 grid(NC / 128, BATCH / 128);   // (16, 64)
    rbf_gemm_kernel<<<grid, 256>>>(inputs, centers, xsq, csq, inv2s, out);
}

// round 10
// speedup vs baseline: 6.1541x; 6.1541x over previous
#include <cuda_runtime.h>
#include <cuda_bf16.h>
#include <cstdint>
#include <math.h>

#define BATCH 8192
#define NC    2048
#define NF    512

#define BM 128
#define BN 128
#define BK 64          // bf16 elems per K-tile (128 bytes/row)
#define NT (NF / BK)   // 8 K-tiles
#define NSTAGE 3

// ---------------- device scratch (no allocs allowed) ----------------
__device__ float g_xsq[BATCH];
__device__ float g_csq[NC];
__device__ float g_inv2s[NC];
__device__ __nv_bfloat16 g_Abf[(size_t)BATCH * NF];
__device__ __nv_bfloat16 g_Bbf[(size_t)NC * NF];

// ---------------- portable PTX helpers (sm_80+ features only) ----------------
__device__ __forceinline__ uint32_t smem_u32(const void* p) {
    uint32_t a;
    asm("{ .reg .u64 t; cvta.to.shared.u64 t, %1; cvt.u32.u64 %0, t; }"
        : "=r"(a) : "l"(p));
    return a;
}

__device__ __forceinline__ void cp_async16(uint32_t dst, const void* src) {
    asm volatile("cp.async.cg.shared.global [%0], [%1], 16;"
                 :: "r"(dst), "l"(src) : "memory");
}
#define CP_COMMIT() asm volatile("cp.async.commit_group;" ::: "memory")
#define CP_WAIT_1() asm volatile("cp.async.wait_group 1;" ::: "memory")
#define CP_WAIT_0() asm volatile("cp.async.wait_group 0;" ::: "memory")

__device__ __forceinline__ void ldsm_x4(uint32_t* r, uint32_t addr) {
    asm volatile("ldmatrix.sync.aligned.m8n8.x4.shared.b16 {%0,%1,%2,%3}, [%4];"
                 : "=r"(r[0]), "=r"(r[1]), "=r"(r[2]), "=r"(r[3]) : "r"(addr));
}

__device__ __forceinline__ void mma_16816(float* c, const uint32_t* a,
                                          uint32_t b0, uint32_t b1) {
    asm volatile("mma.sync.aligned.m16n8k16.row.col.f32.bf16.bf16.f32 "
                 "{%0,%1,%2,%3}, {%4,%5,%6,%7}, {%8,%9}, {%0,%1,%2,%3};"
                 : "+f"(c[0]), "+f"(c[1]), "+f"(c[2]), "+f"(c[3])
                 : "r"(a[0]), "r"(a[1]), "r"(a[2]), "r"(a[3]), "r"(b0), "r"(b1));
}

// ---------------- SMEM layout (dynamic) ----------------
// stage s: A at 1024 + s*32768, B at A+16384; then xsq/csq/inv2s staging.
static constexpr int OFF_STAGE0 = 1024;
static constexpr int STAGE_BYTES = 32768;           // 16K A + 16K B
static constexpr int OFF_XS = OFF_STAGE0 + NSTAGE * STAGE_BYTES;   // 99328
static constexpr int OFF_CS = OFF_XS + 512;
static constexpr int OFF_IS = OFF_CS + 512;
static constexpr int SMEM_TOTAL = OFF_IS + 512;     // 100864 bytes

// ---------------- fused fp32->bf16 convert + row norms ----------------
__global__ void convert_norm_kernel(const float* __restrict__ X,
                                    __nv_bfloat16* __restrict__ Xb,
                                    float* __restrict__ nrm, int rows) {
    int row  = blockIdx.x * (blockDim.x >> 5) + (threadIdx.x >> 5);
    int lane = threadIdx.x & 31;
    if (row >= rows) return;
    const float4* p = reinterpret_cast<const float4*>(X + (size_t)row * NF);
    __nv_bfloat162* q = reinterpret_cast<__nv_bfloat162*>(Xb + (size_t)row * NF);
    float s = 0.f;
    #pragma unroll
    for (int i = 0; i < NF / 4 / 32; i++) {
        int idx = lane + i * 32;
        float4 v = p[idx];
        s += v.x * v.x + v.y * v.y + v.z * v.z + v.w * v.w;
        q[idx * 2]     = __floats2bfloat162_rn(v.x, v.y);
        q[idx * 2 + 1] = __floats2bfloat162_rn(v.z, v.w);
    }
    #pragma unroll
    for (int o = 16; o; o >>= 1) s += __shfl_xor_sync(0xffffffffu, s, o);
    if (lane == 0) nrm[row] = s;
}

__global__ void sigma_kernel(const float* __restrict__ sig,
                             float* __restrict__ out, int n) {
    int i = blockIdx.x * blockDim.x + threadIdx.x;
    if (i < n) {
        float s = sig[i];
        out[i] = 1.0f / (2.0f * s * s);
    }
}

// ---------------- HMMA (mma.sync) GEMM + fused RBF epilogue ----------------
__global__ __launch_bounds__(256)
void rbf_mma_kernel(const __nv_bfloat16* __restrict__ Abf,
                    const __nv_bfloat16* __restrict__ Bbf,
                    const float* __restrict__ xsq,
                    const float* __restrict__ csq,
                    const float* __restrict__ inv2s,
                    float* __restrict__ C) {
    extern __shared__ char smem[];
    const uint32_t sb = smem_u32(smem);
    const int tid = threadIdx.x;
    const int wid = tid >> 5;
    const int lid = tid & 31;
    const int bx = blockIdx.x;           // N tile
    const int by = blockIdx.y;           // M tile
    const int warp_m = wid & 3;          // 4 m-warps * 32 rows
    const int warp_n = wid >> 2;         // 2 n-warps * 64 cols

    // stage per-tile xsq/csq/inv2s
    if (tid < 128) {
        reinterpret_cast<float*>(smem + OFF_XS)[tid] = xsq[by * BM + tid];
        reinterpret_cast<float*>(smem + OFF_CS)[tid] = csq[bx * BN + tid];
        reinterpret_cast<float*>(smem + OFF_IS)[tid] = inv2s[bx * BN + tid];
    }

    const __nv_bfloat16* Ag0 = Abf + (size_t)(by * BM) * NF;
    const __nv_bfloat16* Bg0 = Bbf + (size_t)(bx * BN) * NF;

    // Per-thread tile-load coords: row = tid>>3 (0..31 step 32), chunk = tid&7.
    const int ld_row0 = tid >> 3;
    const int ld_c16  = tid & 7;

    auto load_tile = [&](int kt, int stage) {
        const uint32_t offA = OFF_STAGE0 + stage * STAGE_BYTES;
        const uint32_t offB = offA + 16384;
        const int k0 = kt * BK;
        #pragma unroll
        for (int i = 0; i < 4; i++) {
            int row = ld_row0 + i * 32;
            // swizzled 16B-chunk offset within 128B row
            uint32_t sw = (uint32_t)row * 128 + ((uint32_t)(ld_c16 ^ (row & 7)) << 4);
            cp_async16(sb + offA + sw, Ag0 + (size_t)row * NF + k0 + ld_c16 * 8);
            cp_async16(sb + offB + sw, Bg0 + (size_t)row * NF + k0 + ld_c16 * 8);
        }
    };

    // ldmatrix lane geometry (same for A and B x4): row = base + (lane&15),
    // chunk = kc + (lane>>4).
    const int lrow = lid & 15;
    const int lchk = lid >> 4;
    const int rowA0 = warp_m * 32 + lrow;          // mi=0; mi=1 adds 16
    const int rowB0 = warp_n * 64 + lrow;          // nq adds 16 each
    const uint32_t xA = (uint32_t)(rowA0 & 7);     // +16 keeps low 3 bits
    const uint32_t xB = (uint32_t)(rowB0 & 7);
    const uint32_t rA_off0 = (uint32_t)rowA0 * 128;
    const uint32_t rB_off0 = (uint32_t)rowB0 * 128;

    float acc[2][8][4];
    #pragma unroll
    for (int mi = 0; mi < 2; mi++)
        #pragma unroll
        for (int n = 0; n < 8; n++)
            #pragma unroll
            for (int v = 0; v < 4; v++) acc[mi][n][v] = 0.f;

    // prologue: stages 0,1
    load_tile(0, 0); CP_COMMIT();
    load_tile(1, 1); CP_COMMIT();

    for (int t = 0; t < NT; t++) {
        if (t == NT - 1) { CP_WAIT_0(); } else { CP_WAIT_1(); }
        __syncthreads();
        if (t + 2 < NT) { load_tile(t + 2, (t + 2) % NSTAGE); CP_COMMIT(); }

        const uint32_t baseA = sb + OFF_STAGE0 + (t % NSTAGE) * STAGE_BYTES;
        const uint32_t baseB = baseA + 16384;

        #pragma unroll
        for (int s = 0; s < BK / 16; s++) {        // 4 k16-steps
            const uint32_t cA = (uint32_t)(s * 2 + lchk);
            uint32_t a[2][4];
            ldsm_x4(a[0], baseA + rA_off0 +          (((cA ^ xA) & 7) << 4));
            ldsm_x4(a[1], baseA + rA_off0 + 2048 +   (((cA ^ xA) & 7) << 4));
            uint32_t b[4][4];
            #pragma unroll
            for (int nq = 0; nq < 4; nq++)
                ldsm_x4(b[nq], baseB + rB_off0 + nq * 2048 + (((cA ^ xB) & 7) << 4));
            #pragma unroll
            for (int mi = 0; mi < 2; mi++)
                #pragma unroll
                for (int nq = 0; nq < 4; nq++) {
                    mma_16816(acc[mi][nq * 2 + 0], a[mi], b[nq][0], b[nq][2]);
                    mma_16816(acc[mi][nq * 2 + 1], a[mi], b[nq][1], b[nq][3]);
                }
        }
    }

    // ---------------- fused RBF epilogue on register accumulators ----------------
    const float* xs = reinterpret_cast<const float*>(smem + OFF_XS);
    const float* cs = reinterpret_cast<const float*>(smem + OFF_CS);
    const float* is = reinterpret_cast<const float*>(smem + OFF_IS);
    const int l4 = lid >> 2;
    const int l2 = (lid & 3) * 2;

    #pragma unroll
    for (int mi = 0; mi < 2; mi++) {
        #pragma unroll
        for (int h = 0; h < 2; h++) {            // c0/c1 vs c2/c3 row halves
            const int r = warp_m * 32 + mi * 16 + h * 8 + l4;   // row in tile
            const float xm = xs[r];
            float* crow = C + (size_t)(by * BM + r) * NC + bx * BN + warp_n * 64;
            #pragma unroll
            for (int n = 0; n < 8; n++) {
                const int cidx = n * 8 + l2;
                float d0 = fmaf(-2.0f, acc[mi][n][h * 2 + 0], xm + cs[warp_n * 64 + cidx]);
                float d1 = fmaf(-2.0f, acc[mi][n][h * 2 + 1], xm + cs[warp_n * 64 + cidx + 1]);
                float2 o;
                o.x = __expf(-fmaxf(d0, 0.0f) * is[warp_n * 64 + cidx]);
                o.y = __expf(-fmaxf(d1, 0.0f) * is[warp_n * 64 + cidx + 1]);
                *reinterpret_cast<float2*>(crow + cidx) = o;
            }
        }
    }
}

// ---------------- launch ----------------
extern "C" void kernel_launch(void* const* d_in, const int* in_sizes, int n_in,
                              void* d_out, int out_size) {
    const float* inputs  = (const float*)d_in[0];
    const float* centers = (const float*)d_in[1];
    const float* sigmas  = (const float*)d_in[2];
    float* out = (float*)d_out;

    float *xsq, *csq, *inv2s;
    __nv_bfloat16 *Abf, *Bbf;
    cudaGetSymbolAddress((void**)&xsq,   g_xsq);
    cudaGetSymbolAddress((void**)&csq,   g_csq);
    cudaGetSymbolAddress((void**)&inv2s, g_inv2s);
    cudaGetSymbolAddress((void**)&Abf,   g_Abf);
    cudaGetSymbolAddress((void**)&Bbf,   g_Bbf);

    cudaFuncSetAttribute(rbf_mma_kernel,
                         cudaFuncAttributeMaxDynamicSharedMemorySize, SMEM_TOTAL);

    convert_norm_kernel<<<BATCH / 8, 256>>>(inputs, Abf, xsq, BATCH);
    convert_norm_kernel<<<NC / 8, 256>>>(centers, Bbf, csq, NC);
    sigma_kernel<<<NC / 256, 256>>>(sigmas, inv2s, NC);

    dim3 grid(NC / BN, BATCH / BM);   // (16, 64)
    rbf_mma_kernel<<<grid, 256, SMEM_TOTAL>>>(Abf, Bbf, xsq, csq, inv2s, out);
}